// round 1
// baseline (speedup 1.0000x reference)
#include <cuda_runtime.h>

// ---------------------------------------------------------------------------
// NextVisitTime attention, restructured:
//   q = uq[user] + (tq[hour] + bq)        (per-user / per-timeslot GEMMs)
//   scores = scale*(us[b] + ts[hour])     (tiny precomputed tables)
//   out = softmax(scores) @ W2 + bu,  W2[h*24+t] = v[t,h] . Wu_h
// Only bulk work left: [65536 x 96] @ [96 x 256] fp32 GEMM -> FFMA2 (f32x2).
// ---------------------------------------------------------------------------

#define T_SLOTS 24
#define D_MODEL 256
#define B_BATCH 512
#define S_SEQ   128
#define N_ROWS  (B_BATCH * S_SEQ)   // 65536
#define H_HEADS 4
#define HD      64
#define J_DIM   (H_HEADS * T_SLOTS) // 96

__device__ float g_k [T_SLOTS * D_MODEL];
__device__ float g_v [T_SLOTS * D_MODEL];
__device__ float g_tq[T_SLOTS * D_MODEL];
__device__ float g_uq[B_BATCH * D_MODEL];
__device__ float g_ts[T_SLOTS * J_DIM];
__device__ float g_us[B_BATCH * J_DIM];
__device__ float g_W2[J_DIM * D_MODEL];

// ---- f32x2 helpers (FFMA2 is only reachable via hand-written PTX) ----------
__device__ __forceinline__ unsigned long long pack_dup(float x) {
    unsigned long long r;
    asm("mov.b64 %0, {%1, %1};" : "=l"(r) : "f"(x));
    return r;
}
__device__ __forceinline__ unsigned long long pack2(float x, float y) {
    unsigned long long r;
    asm("mov.b64 %0, {%1, %2};" : "=l"(r) : "f"(x), "f"(y));
    return r;
}
__device__ __forceinline__ void fma2(unsigned long long &c,
                                     unsigned long long a,
                                     unsigned long long b) {
    asm("fma.rn.f32x2 %0, %1, %2, %0;" : "+l"(c) : "l"(a), "l"(b));
}
__device__ __forceinline__ float2 unpack2(unsigned long long v) {
    float2 r;
    asm("mov.b64 {%0, %1}, %2;" : "=f"(r.x), "=f"(r.y) : "l"(v));
    return r;
}

// ---- P1: k, v, tq(+bq) — [24,256] rows, one block per (t, which) -----------
__global__ void precompute_kvtq(const float* __restrict__ ts_emb,
                                const float* __restrict__ Wk, const float* __restrict__ bk,
                                const float* __restrict__ Wv, const float* __restrict__ bv,
                                const float* __restrict__ Wq, const float* __restrict__ bq) {
    __shared__ float srow[D_MODEL];
    int t = blockIdx.x;
    int z = blockIdx.y;
    int d = threadIdx.x;
    srow[d] = ts_emb[t * D_MODEL + d];
    __syncthreads();
    const float* W; const float* bias; float* outp;
    if (z == 0)      { W = Wk;                       bias = bk; outp = g_k;  }
    else if (z == 1) { W = Wv;                       bias = bv; outp = g_v;  }
    else             { W = Wq + D_MODEL * D_MODEL;   bias = bq; outp = g_tq; } // rows 256..511 of Wq, fold bq
    float acc = bias[d];
    #pragma unroll 8
    for (int c = 0; c < D_MODEL; c++)
        acc = fmaf(srow[c], W[c * D_MODEL + d], acc);
    outp[t * D_MODEL + d] = acc;
}

// ---- P2: uq[b] = user_pref[user[b]] @ Wq[0:256] (8 users per block) --------
__global__ void precompute_uq(const int* __restrict__ user,
                              const float* __restrict__ upt,
                              const float* __restrict__ Wq) {
    __shared__ float srow[8][D_MODEL];
    int b0 = blockIdx.x * 8;
    int d  = threadIdx.x;
    #pragma unroll
    for (int i = 0; i < 8; i++)
        srow[i][d] = upt[(size_t)user[b0 + i] * D_MODEL + d];
    __syncthreads();
    float acc[8];
    #pragma unroll
    for (int i = 0; i < 8; i++) acc[i] = 0.0f;
    for (int c = 0; c < D_MODEL; c++) {
        float w = Wq[c * D_MODEL + d];
        #pragma unroll
        for (int i = 0; i < 8; i++) acc[i] = fmaf(srow[i][c], w, acc[i]);
    }
    #pragma unroll
    for (int i = 0; i < 8; i++) g_uq[(b0 + i) * D_MODEL + d] = acc[i];
}

// ---- P3a: ts[th][h*24+t] = scale * (tq[th]+bq)_h . k[t]_h ------------------
__global__ void precompute_ts() {
    int th = blockIdx.x;
    int j  = threadIdx.x;       // 0..95
    int h = j / T_SLOTS, t = j % T_SLOTS;
    const float* a = g_tq + th * D_MODEL + h * HD;
    const float* b = g_k  + t  * D_MODEL + h * HD;
    float acc = 0.0f;
    #pragma unroll
    for (int e = 0; e < HD; e++) acc = fmaf(a[e], b[e], acc);
    g_ts[th * J_DIM + j] = acc * 0.125f;   // scale = 1/sqrt(64)
}

// ---- P3b: W2[h*24+t][d] = sum_e v[t][h*64+e] * Wu[h*64+e][d] ---------------
__global__ void precompute_w2(const float* __restrict__ Wu) {
    int j = blockIdx.x;
    int h = j / T_SLOTS, t = j % T_SLOTS;
    int d = threadIdx.x;
    __shared__ float vv[HD];
    if (d < HD) vv[d] = g_v[t * D_MODEL + h * HD + d];
    __syncthreads();
    const float* W = Wu + (h * HD) * D_MODEL + d;
    float acc = 0.0f;
    #pragma unroll 8
    for (int e = 0; e < HD; e++) acc = fmaf(vv[e], W[e * D_MODEL], acc);
    g_W2[j * D_MODEL + d] = acc;
}

// ---- P4: us[b][h*24+t] = scale * uq[b]_h . k[t]_h --------------------------
__global__ void precompute_us() {
    int b = blockIdx.x;
    int j = threadIdx.x;
    int h = j / T_SLOTS, t = j % T_SLOTS;
    const float* a = g_uq + b * D_MODEL + h * HD;
    const float* k = g_k  + t * D_MODEL + h * HD;
    float acc = 0.0f;
    #pragma unroll
    for (int e = 0; e < HD; e++) acc = fmaf(a[e], k[e], acc);
    g_us[b * J_DIM + j] = acc * 0.125f;
}

// ---- Main: per block 64 rows -> softmax + [64x96]@[96x256] FFMA2 GEMM ------
// SMEM layout (floats): W2 24576 | att 64*100 (padded) | ts 2304 | us 96
#define SM_W2   0
#define SM_ATT  24576
#define ATT_PITCH 100
#define SM_TS   (SM_ATT + 64 * ATT_PITCH)       // 30976
#define SM_US   (SM_TS + T_SLOTS * J_DIM)       // 33280
#define SM_FLOATS (SM_US + J_DIM)               // 33376
#define SM_BYTES  (SM_FLOATS * 4)               // 133504

__global__ __launch_bounds__(256, 1) void main_kernel(
    const int* __restrict__ hour, const int* __restrict__ hmask,
    const float* __restrict__ bu, float* __restrict__ out)
{
    extern __shared__ float sm[];
    float* sW2  = sm + SM_W2;
    float* sAtt = sm + SM_ATT;
    float* sTs  = sm + SM_TS;
    float* sUs  = sm + SM_US;

    int tid = threadIdx.x;
    int n0  = blockIdx.x * 64;
    int b   = n0 >> 7;            // 64 | 128 -> whole block in one batch row

    // cooperative loads
    {
        const float4* s1 = (const float4*)g_W2;
        float4* d1 = (float4*)sW2;
        #pragma unroll
        for (int i = 0; i < 24; i++) d1[tid + i * 256] = s1[tid + i * 256];
        const float4* s2 = (const float4*)g_ts;
        float4* d2 = (float4*)sTs;
        for (int i = tid; i < (T_SLOTS * J_DIM) / 4; i += 256) d2[i] = s2[i];
        if (tid < J_DIM / 4)
            ((float4*)sUs)[tid] = ((const float4*)(g_us + b * J_DIM))[tid];
    }
    __syncthreads();

    // ---- phase 1: one thread per (row, head) masked softmax ----
    {
        int r = tid >> 2, h = tid & 3;
        int n = n0 + r;
        int hh = __ldg(hour + n);
        int msk[T_SLOTS];
        const int4* mp = (const int4*)(hmask + (size_t)n * T_SLOTS);
        #pragma unroll
        for (int i = 0; i < 6; i++) {
            int4 q = mp[i];
            msk[4*i] = q.x; msk[4*i+1] = q.y; msk[4*i+2] = q.z; msk[4*i+3] = q.w;
        }
        const float* usb = sUs + h * T_SLOTS;
        const float* tsb = sTs + hh * J_DIM + h * T_SLOTS;
        float sc[T_SLOTS];
        float mx = -3.0e38f;
        #pragma unroll
        for (int t = 0; t < T_SLOTS; t++) {
            sc[t] = msk[t] ? -1e9f : (usb[t] + tsb[t]);
            mx = fmaxf(mx, sc[t]);
        }
        float s = 0.0f;
        #pragma unroll
        for (int t = 0; t < T_SLOTS; t++) {
            float e = __expf(sc[t] - mx);
            sc[t] = e; s += e;
        }
        float inv = 1.0f / s;
        float* ar = sAtt + r * ATT_PITCH + h * T_SLOTS;
        #pragma unroll
        for (int t = 0; t < T_SLOTS; t++) ar[t] = sc[t] * inv;
    }
    __syncthreads();

    // ---- phase 2: [64 x 96] @ [96 x 256], 4 rows x 16 cols per thread ----
    int rg = tid >> 4, cg = tid & 15;
    int r0 = rg * 4, c0 = cg * 16;
    unsigned long long acc[4][8];
    #pragma unroll
    for (int i = 0; i < 8; i++) {
        unsigned long long bv = pack2(__ldg(bu + c0 + 2*i), __ldg(bu + c0 + 2*i + 1));
        #pragma unroll
        for (int rr = 0; rr < 4; rr++) acc[rr][i] = bv;
    }
    const unsigned long long* w2p = (const unsigned long long*)sW2 + (c0 >> 1);
    const float* ap = sAtt + r0 * ATT_PITCH;
    #pragma unroll 2
    for (int j = 0; j < J_DIM; j++) {
        unsigned long long w[8];
        #pragma unroll
        for (int i = 0; i < 8; i++) w[i] = w2p[j * (D_MODEL/2) + i];
        #pragma unroll
        for (int rr = 0; rr < 4; rr++) {
            unsigned long long a = pack_dup(ap[rr * ATT_PITCH + j]);
            #pragma unroll
            for (int i = 0; i < 8; i++) fma2(acc[rr][i], a, w[i]);
        }
    }
    #pragma unroll
    for (int rr = 0; rr < 4; rr++) {
        float4* o = (float4*)(out + (size_t)(n0 + r0 + rr) * D_MODEL + c0);
        #pragma unroll
        for (int i = 0; i < 4; i++) {
            float2 lo = unpack2(acc[rr][2*i]);
            float2 hi = unpack2(acc[rr][2*i + 1]);
            o[i] = make_float4(lo.x, lo.y, hi.x, hi.y);
        }
    }
}

extern "C" void kernel_launch(void* const* d_in, const int* in_sizes, int n_in,
                              void* d_out, int out_size) {
    const float* ts_emb = (const float*)d_in[0];
    const int*   user   = (const int*)  d_in[1];
    const int*   hour   = (const int*)  d_in[2];
    const int*   hmask  = (const int*)  d_in[3];
    const float* upt    = (const float*)d_in[4];
    const float* Wq     = (const float*)d_in[5];
    const float* bq     = (const float*)d_in[6];
    const float* Wk     = (const float*)d_in[7];
    const float* bk     = (const float*)d_in[8];
    const float* Wv     = (const float*)d_in[9];
    const float* bv     = (const float*)d_in[10];
    const float* Wu     = (const float*)d_in[11];
    const float* bu     = (const float*)d_in[12];
    float* out = (float*)d_out;

    precompute_kvtq<<<dim3(T_SLOTS, 3), D_MODEL>>>(ts_emb, Wk, bk, Wv, bv, Wq, bq);
    precompute_uq<<<B_BATCH / 8, D_MODEL>>>(user, upt, Wq);
    precompute_ts<<<T_SLOTS, J_DIM>>>();
    precompute_w2<<<J_DIM, D_MODEL>>>(Wu);
    precompute_us<<<B_BATCH, J_DIM>>>();

    cudaFuncSetAttribute(main_kernel, cudaFuncAttributeMaxDynamicSharedMemorySize, SM_BYTES);
    main_kernel<<<N_ROWS / 64, 256, SM_BYTES>>>(hour, hmask, bu, out);
}

// round 2
// speedup vs baseline: 1.8679x; 1.8679x over previous
#include <cuda_runtime.h>

// ---------------------------------------------------------------------------
// NextVisitTime attention, restructured:
//   q = uq[user] + (tq[hour] + bq)        (per-user / per-timeslot GEMMs)
//   scores = scale*(us[b] + ts[hour])     (tiny precomputed tables)
//   out = softmax(scores) @ W2 + bu,  W2[h*24+t] = v[t,h] . Wu_h
// Bulk work: [65536 x 96] @ [96 x 256] fp32 GEMM -> FFMA2 (f32x2),
// with conflict-free/broadcast LDS weight reads (interleaved column map).
// ---------------------------------------------------------------------------

#define T_SLOTS 24
#define D_MODEL 256
#define B_BATCH 512
#define S_SEQ   128
#define N_ROWS  (B_BATCH * S_SEQ)   // 65536
#define H_HEADS 4
#define HD      64
#define J_DIM   (H_HEADS * T_SLOTS) // 96

__device__ float g_k [T_SLOTS * D_MODEL];
__device__ float g_v [T_SLOTS * D_MODEL];
__device__ float g_tq[T_SLOTS * D_MODEL];
__device__ float g_uq[B_BATCH * D_MODEL];
__device__ float g_ts[T_SLOTS * J_DIM];
__device__ float g_us[B_BATCH * J_DIM];
__device__ float g_W2[J_DIM * D_MODEL];

// ---- f32x2 helpers (FFMA2 is only reachable via hand-written PTX) ----------
__device__ __forceinline__ unsigned long long pack_dup(float x) {
    unsigned long long r;
    asm("mov.b64 %0, {%1, %1};" : "=l"(r) : "f"(x));
    return r;
}
__device__ __forceinline__ unsigned long long pack2(float x, float y) {
    unsigned long long r;
    asm("mov.b64 %0, {%1, %2};" : "=l"(r) : "f"(x), "f"(y));
    return r;
}
__device__ __forceinline__ void fma2(unsigned long long &c,
                                     unsigned long long a,
                                     unsigned long long b) {
    asm("fma.rn.f32x2 %0, %1, %2, %0;" : "+l"(c) : "l"(a), "l"(b));
}
__device__ __forceinline__ float2 unpack2(unsigned long long v) {
    float2 r;
    asm("mov.b64 {%0, %1}, %2;" : "=f"(r.x), "=f"(r.y) : "l"(v));
    return r;
}

// ===========================================================================
// Kernel A: layer-1 GEMMs.
//   blocks [0,72):  k / v / tq(+bq) rows  (t = bx%24, z = bx/24)
//   blocks [72,136): uq for 8 users each
// ===========================================================================
__global__ __launch_bounds__(256) void preA(
    const float* __restrict__ ts_emb,
    const float* __restrict__ Wk, const float* __restrict__ bk,
    const float* __restrict__ Wv, const float* __restrict__ bv,
    const float* __restrict__ Wq, const float* __restrict__ bq,
    const int*   __restrict__ user,
    const float* __restrict__ upt)
{
    __shared__ float srow[8][D_MODEL];
    int bx = blockIdx.x;
    int d  = threadIdx.x;

    if (bx < 72) {
        int t = bx % 24, z = bx / 24;
        srow[0][d] = ts_emb[t * D_MODEL + d];
        __syncthreads();
        const float* W; const float* bias; float* outp;
        if (z == 0)      { W = Wk;                     bias = bk; outp = g_k;  }
        else if (z == 1) { W = Wv;                     bias = bv; outp = g_v;  }
        else             { W = Wq + D_MODEL * D_MODEL; bias = bq; outp = g_tq; }
        float a0 = bias[d], a1 = 0.f, a2 = 0.f, a3 = 0.f;
        #pragma unroll 4
        for (int c = 0; c < D_MODEL; c += 4) {
            a0 = fmaf(srow[0][c+0], W[(c+0) * D_MODEL + d], a0);
            a1 = fmaf(srow[0][c+1], W[(c+1) * D_MODEL + d], a1);
            a2 = fmaf(srow[0][c+2], W[(c+2) * D_MODEL + d], a2);
            a3 = fmaf(srow[0][c+3], W[(c+3) * D_MODEL + d], a3);
        }
        outp[t * D_MODEL + d] = (a0 + a1) + (a2 + a3);
    } else {
        int b0 = (bx - 72) * 8;
        #pragma unroll
        for (int i = 0; i < 8; i++)
            srow[i][d] = upt[(size_t)user[b0 + i] * D_MODEL + d];
        __syncthreads();
        float acc[8];
        #pragma unroll
        for (int i = 0; i < 8; i++) acc[i] = 0.0f;
        for (int c = 0; c < D_MODEL; c++) {
            float w = Wq[c * D_MODEL + d];
            #pragma unroll
            for (int i = 0; i < 8; i++) acc[i] = fmaf(srow[i][c], w, acc[i]);
        }
        #pragma unroll
        for (int i = 0; i < 8; i++) g_uq[(b0 + i) * D_MODEL + d] = acc[i];
    }
}

// ===========================================================================
// Kernel B: second-stage precompute.
//   blocks [0,96):    W2 row j = bx
//   blocks [96,105):  ts flat (2304 elems)
//   blocks [105,297): us flat (49152 elems)
// ===========================================================================
__device__ __forceinline__ float dot64(const float* __restrict__ a,
                                       const float* __restrict__ b) {
    float s0 = 0.f, s1 = 0.f, s2 = 0.f, s3 = 0.f;
    #pragma unroll
    for (int e = 0; e < HD; e += 4) {
        s0 = fmaf(a[e+0], b[e+0], s0);
        s1 = fmaf(a[e+1], b[e+1], s1);
        s2 = fmaf(a[e+2], b[e+2], s2);
        s3 = fmaf(a[e+3], b[e+3], s3);
    }
    return (s0 + s1) + (s2 + s3);
}

__global__ __launch_bounds__(256) void preB(const float* __restrict__ Wu)
{
    int bx  = blockIdx.x;
    int tid = threadIdx.x;

    if (bx < 96) {                                  // W2
        int j = bx;
        int h = j / T_SLOTS, t = j % T_SLOTS;
        __shared__ float vv[HD];
        if (tid < HD) vv[tid] = g_v[t * D_MODEL + h * HD + tid];
        __syncthreads();
        const float* W = Wu + (h * HD) * D_MODEL + tid;
        float a0 = 0.f, a1 = 0.f, a2 = 0.f, a3 = 0.f;
        #pragma unroll 4
        for (int e = 0; e < HD; e += 4) {
            a0 = fmaf(vv[e+0], W[(e+0) * D_MODEL], a0);
            a1 = fmaf(vv[e+1], W[(e+1) * D_MODEL], a1);
            a2 = fmaf(vv[e+2], W[(e+2) * D_MODEL], a2);
            a3 = fmaf(vv[e+3], W[(e+3) * D_MODEL], a3);
        }
        g_W2[j * D_MODEL + tid] = (a0 + a1) + (a2 + a3);
    } else if (bx < 105) {                          // ts
        int idx = (bx - 96) * 256 + tid;
        if (idx < T_SLOTS * J_DIM) {
            int th = idx / J_DIM, jj = idx % J_DIM;
            int h = jj / T_SLOTS, t = jj % T_SLOTS;
            g_ts[idx] = dot64(g_tq + th * D_MODEL + h * HD,
                              g_k  + t  * D_MODEL + h * HD) * 0.125f;
        }
    } else {                                        // us
        int idx = (bx - 105) * 256 + tid;           // < 49152 exactly
        int b = idx / J_DIM, jj = idx % J_DIM;
        int h = jj / T_SLOTS, t = jj % T_SLOTS;
        g_us[idx] = dot64(g_uq + b * D_MODEL + h * HD,
                          g_k  + t * D_MODEL + h * HD) * 0.125f;
    }
}

// ===========================================================================
// Main: per block 64 rows -> softmax + [64x96]@[96x256] FFMA2 GEMM
// SMEM (floats): W2 24576 | att 64*100 (padded) | ts 2304 | us 96
// ===========================================================================
#define SM_W2   0
#define SM_ATT  24576
#define ATT_PITCH 100
#define SM_TS   (SM_ATT + 64 * ATT_PITCH)       // 30976
#define SM_US   (SM_TS + T_SLOTS * J_DIM)       // 33280
#define SM_FLOATS (SM_US + J_DIM)               // 33376
#define SM_BYTES  (SM_FLOATS * 4)               // 133504

__global__ __launch_bounds__(256, 1) void main_kernel(
    const int* __restrict__ hour, const int* __restrict__ hmask,
    const float* __restrict__ bu, float* __restrict__ out)
{
    extern __shared__ float sm[];
    float* sW2  = sm + SM_W2;
    float* sAtt = sm + SM_ATT;
    float* sTs  = sm + SM_TS;
    float* sUs  = sm + SM_US;

    int tid = threadIdx.x;
    int n0  = blockIdx.x * 64;
    int b   = n0 >> 7;            // 64 | 128 -> whole block in one batch row

    // cooperative loads
    {
        const float4* s1 = (const float4*)g_W2;
        float4* d1 = (float4*)sW2;
        #pragma unroll
        for (int i = 0; i < 24; i++) d1[tid + i * 256] = s1[tid + i * 256];
        const float4* s2 = (const float4*)g_ts;
        float4* d2 = (float4*)sTs;
        for (int i = tid; i < (T_SLOTS * J_DIM) / 4; i += 256) d2[i] = s2[i];
        if (tid < J_DIM / 4)
            ((float4*)sUs)[tid] = ((const float4*)(g_us + b * J_DIM))[tid];
    }
    __syncthreads();

    // ---- phase 1: one thread per (row, head) masked softmax ----
    {
        int r = tid >> 2, h = tid & 3;
        int n = n0 + r;
        int hh = __ldg(hour + n);
        int msk[T_SLOTS];
        const int4* mp = (const int4*)(hmask + (size_t)n * T_SLOTS);
        #pragma unroll
        for (int i = 0; i < 6; i++) {
            int4 q = mp[i];
            msk[4*i] = q.x; msk[4*i+1] = q.y; msk[4*i+2] = q.z; msk[4*i+3] = q.w;
        }
        const float* usb = sUs + h * T_SLOTS;
        const float* tsb = sTs + hh * J_DIM + h * T_SLOTS;
        float sc[T_SLOTS];
        float mx = -3.0e38f;
        #pragma unroll
        for (int t = 0; t < T_SLOTS; t++) {
            sc[t] = msk[t] ? -1e9f : (usb[t] + tsb[t]);
            mx = fmaxf(mx, sc[t]);
        }
        float s = 0.0f;
        #pragma unroll
        for (int t = 0; t < T_SLOTS; t++) {
            float e = __expf(sc[t] - mx);
            sc[t] = e; s += e;
        }
        float inv = 1.0f / s;
        float* ar = sAtt + r * ATT_PITCH + h * T_SLOTS;
        #pragma unroll
        for (int t = 0; t < T_SLOTS; t++) ar[t] = sc[t] * inv;
    }
    __syncthreads();

    // ---- phase 2: [64 x 96] @ [96 x 256], 4 rows x 16 interleaved col-pairs
    // Thread (rg,cg): rows r0..r0+3, u64 columns {cg + i*16 : i=0..7}.
    // For fixed i, lanes 0..15 read 16 consecutive u64 (all 32 banks,
    // conflict-free); lanes 16..31 read identical addresses (broadcast).
    int rg = tid >> 4, cg = tid & 15;
    int r0 = rg * 4;
    unsigned long long acc[4][8];
    #pragma unroll
    for (int i = 0; i < 8; i++) {
        int cp = cg + i * 16;    // u64 column index (float cols 2cp, 2cp+1)
        unsigned long long bv = pack2(__ldg(bu + 2*cp), __ldg(bu + 2*cp + 1));
        #pragma unroll
        for (int rr = 0; rr < 4; rr++) acc[rr][i] = bv;
    }
    const unsigned long long* w2p = (const unsigned long long*)sW2;
    const float* ap = sAtt + r0 * ATT_PITCH;
    #pragma unroll 2
    for (int j = 0; j < J_DIM; j++) {
        unsigned long long w[8];
        #pragma unroll
        for (int i = 0; i < 8; i++) w[i] = w2p[j * (D_MODEL/2) + cg + i * 16];
        #pragma unroll
        for (int rr = 0; rr < 4; rr++) {
            unsigned long long a = pack_dup(ap[rr * ATT_PITCH + j]);
            #pragma unroll
            for (int i = 0; i < 8; i++) fma2(acc[rr][i], a, w[i]);
        }
    }
    #pragma unroll
    for (int rr = 0; rr < 4; rr++) {
        float2* orow = (float2*)(out + (size_t)(n0 + r0 + rr) * D_MODEL);
        #pragma unroll
        for (int i = 0; i < 8; i++) {
            float2 v = unpack2(acc[rr][i]);
            orow[cg + i * 16] = v;
        }
    }
}

extern "C" void kernel_launch(void* const* d_in, const int* in_sizes, int n_in,
                              void* d_out, int out_size) {
    const float* ts_emb = (const float*)d_in[0];
    const int*   user   = (const int*)  d_in[1];
    const int*   hour   = (const int*)  d_in[2];
    const int*   hmask  = (const int*)  d_in[3];
    const float* upt    = (const float*)d_in[4];
    const float* Wq     = (const float*)d_in[5];
    const float* bq     = (const float*)d_in[6];
    const float* Wk     = (const float*)d_in[7];
    const float* bk     = (const float*)d_in[8];
    const float* Wv     = (const float*)d_in[9];
    const float* bv     = (const float*)d_in[10];
    const float* Wu     = (const float*)d_in[11];
    const float* bu     = (const float*)d_in[12];
    float* out = (float*)d_out;

    preA<<<72 + B_BATCH / 8, 256>>>(ts_emb, Wk, bk, Wv, bv, Wq, bq, user, upt);
    preB<<<96 + 9 + 192, 256>>>(Wu);

    cudaFuncSetAttribute(main_kernel, cudaFuncAttributeMaxDynamicSharedMemorySize, SM_BYTES);
    main_kernel<<<N_ROWS / 64, 256, SM_BYTES>>>(hour, hmask, bu, out);
}

// round 3
// speedup vs baseline: 2.2045x; 1.1802x over previous
#include <cuda_runtime.h>

// ---------------------------------------------------------------------------
// NextVisitTime attention, restructured:
//   q = uq[user] + (tq[hour] + bq)        (per-user / per-timeslot GEMMs)
//   scores = scale*(us[b] + ts[hour])     (tiny precomputed tables)
//   out = softmax(scores) @ W2 + bu,  W2[h*24+t] = v[t,h] . Wu_h
// Bulk work: [65536 x 96] @ [96 x 256] fp32 -> FFMA2 with LDS.128 weights,
// pre-duplicated attention values, float4 stores.
// ---------------------------------------------------------------------------

#define T_SLOTS 24
#define D_MODEL 256
#define B_BATCH 512
#define S_SEQ   128
#define N_ROWS  (B_BATCH * S_SEQ)   // 65536
#define H_HEADS 4
#define HD      64
#define J_DIM   (H_HEADS * T_SLOTS) // 96

__device__ float g_k  [T_SLOTS * D_MODEL];
__device__ float g_v  [T_SLOTS * D_MODEL];
__device__ float g_tq [T_SLOTS * D_MODEL];
__device__ float g_uqA[B_BATCH * D_MODEL];   // partial over c in [0,128)
__device__ float g_uqB[B_BATCH * D_MODEL];   // partial over c in [128,256)
__device__ float g_ts [T_SLOTS * J_DIM];
__device__ float g_us [B_BATCH * J_DIM];
__device__ float g_W2 [J_DIM * D_MODEL];

typedef unsigned long long u64;

// ---- f32x2 helpers (FFMA2 only reachable via hand-written PTX) -------------
__device__ __forceinline__ u64 pack_dup(float x) {
    u64 r; asm("mov.b64 %0, {%1, %1};" : "=l"(r) : "f"(x)); return r;
}
__device__ __forceinline__ u64 pack2(float x, float y) {
    u64 r; asm("mov.b64 %0, {%1, %2};" : "=l"(r) : "f"(x), "f"(y)); return r;
}
__device__ __forceinline__ void fma2(u64 &c, u64 a, u64 b) {
    asm("fma.rn.f32x2 %0, %1, %2, %0;" : "+l"(c) : "l"(a), "l"(b));
}
__device__ __forceinline__ float2 unpack2(u64 v) {
    float2 r; asm("mov.b64 {%0, %1}, %2;" : "=f"(r.x), "=f"(r.y) : "l"(v)); return r;
}

// ===========================================================================
// Kernel A: layer-1 GEMMs.
//   blocks [0,72):    k / v / tq(+bq) rows (t = bx%24, z = bx/24)
//   blocks [72,200):  uq split: group g = bx-72; users (g>>1)*8, c-half g&1
// ===========================================================================
__global__ __launch_bounds__(256) void preA(
    const float* __restrict__ ts_emb,
    const float* __restrict__ Wk, const float* __restrict__ bk,
    const float* __restrict__ Wv, const float* __restrict__ bv,
    const float* __restrict__ Wq, const float* __restrict__ bq,
    const int*   __restrict__ user,
    const float* __restrict__ upt)
{
    __shared__ float srow[8][D_MODEL];
    int bx = blockIdx.x;
    int d  = threadIdx.x;

    if (bx < 72) {
        int t = bx % 24, z = bx / 24;
        srow[0][d] = ts_emb[t * D_MODEL + d];
        __syncthreads();
        const float* W; const float* bias; float* outp;
        if (z == 0)      { W = Wk;                     bias = bk; outp = g_k;  }
        else if (z == 1) { W = Wv;                     bias = bv; outp = g_v;  }
        else             { W = Wq + D_MODEL * D_MODEL; bias = bq; outp = g_tq; }
        float a[8];
        a[0] = bias[d];
        #pragma unroll
        for (int i = 1; i < 8; i++) a[i] = 0.f;
        #pragma unroll 4
        for (int c = 0; c < D_MODEL; c += 8) {
            #pragma unroll
            for (int u = 0; u < 8; u++)
                a[u] = fmaf(srow[0][c + u], W[(c + u) * D_MODEL + d], a[u]);
        }
        outp[t * D_MODEL + d] =
            ((a[0] + a[1]) + (a[2] + a[3])) + ((a[4] + a[5]) + (a[6] + a[7]));
    } else {
        int g  = bx - 72;            // 0..127
        int b0 = (g >> 1) * 8;       // 8-user group
        int ch = (g & 1) * 128;      // c-half offset
        float* outp = (g & 1) ? g_uqB : g_uqA;
        if (d < 128) {
            #pragma unroll
            for (int i = 0; i < 8; i++)
                srow[i][d] = upt[(size_t)user[b0 + i] * D_MODEL + ch + d];
        }
        __syncthreads();
        float acc[8];
        #pragma unroll
        for (int i = 0; i < 8; i++) acc[i] = 0.0f;
        #pragma unroll 8
        for (int c = 0; c < 128; c++) {
            float w = Wq[(ch + c) * D_MODEL + d];
            #pragma unroll
            for (int i = 0; i < 8; i++) acc[i] = fmaf(srow[i][c], w, acc[i]);
        }
        #pragma unroll
        for (int i = 0; i < 8; i++) outp[(b0 + i) * D_MODEL + d] = acc[i];
    }
}

// ===========================================================================
// Kernel B: second-stage precompute.
//   blocks [0,96):    W2 row j = bx
//   blocks [96,105):  ts flat (2304 elems)
//   blocks [105,297): us flat (49152 elems)
// ===========================================================================
__global__ __launch_bounds__(256) void preB(const float* __restrict__ Wu)
{
    int bx  = blockIdx.x;
    int tid = threadIdx.x;

    if (bx < 96) {                                  // W2
        int j = bx;
        int h = j / T_SLOTS, t = j % T_SLOTS;
        __shared__ float vv[HD];
        if (tid < HD) vv[tid] = g_v[t * D_MODEL + h * HD + tid];
        __syncthreads();
        const float* W = Wu + (h * HD) * D_MODEL + tid;
        float a[8];
        #pragma unroll
        for (int i = 0; i < 8; i++) a[i] = 0.f;
        #pragma unroll 2
        for (int e = 0; e < HD; e += 8) {
            #pragma unroll
            for (int u = 0; u < 8; u++)
                a[u] = fmaf(vv[e + u], W[(e + u) * D_MODEL], a[u]);
        }
        g_W2[j * D_MODEL + tid] =
            ((a[0] + a[1]) + (a[2] + a[3])) + ((a[4] + a[5]) + (a[6] + a[7]));
    } else if (bx < 105) {                          // ts = (tq . k) * scale
        int idx = (bx - 96) * 256 + tid;
        if (idx < T_SLOTS * J_DIM) {
            int th = idx / J_DIM, jj = idx % J_DIM;
            int h = jj / T_SLOTS, t = jj % T_SLOTS;
            const float4* a4 = (const float4*)(g_tq + th * D_MODEL + h * HD);
            const float4* k4 = (const float4*)(g_k  + t  * D_MODEL + h * HD);
            float s0 = 0.f, s1 = 0.f, s2 = 0.f, s3 = 0.f;
            #pragma unroll
            for (int e = 0; e < HD / 4; e++) {
                float4 av = a4[e], kv = k4[e];
                s0 = fmaf(av.x, kv.x, s0); s1 = fmaf(av.y, kv.y, s1);
                s2 = fmaf(av.z, kv.z, s2); s3 = fmaf(av.w, kv.w, s3);
            }
            g_ts[idx] = ((s0 + s1) + (s2 + s3)) * 0.125f;
        }
    } else {                                        // us = ((uqA+uqB) . k)*scale
        int idx = (bx - 105) * 256 + tid;           // < 49152 exactly
        int b = idx / J_DIM, jj = idx % J_DIM;
        int h = jj / T_SLOTS, t = jj % T_SLOTS;
        const float4* aA = (const float4*)(g_uqA + b * D_MODEL + h * HD);
        const float4* aB = (const float4*)(g_uqB + b * D_MODEL + h * HD);
        const float4* k4 = (const float4*)(g_k   + t * D_MODEL + h * HD);
        float s0 = 0.f, s1 = 0.f, s2 = 0.f, s3 = 0.f;
        #pragma unroll
        for (int e = 0; e < HD / 4; e++) {
            float4 av = aA[e], bv = aB[e], kv = k4[e];
            s0 = fmaf(av.x + bv.x, kv.x, s0);
            s1 = fmaf(av.y + bv.y, kv.y, s1);
            s2 = fmaf(av.z + bv.z, kv.z, s2);
            s3 = fmaf(av.w + bv.w, kv.w, s3);
        }
        g_us[idx] = ((s0 + s1) + (s2 + s3)) * 0.125f;
    }
}

// ===========================================================================
// Main: per block 64 rows -> softmax + [64x96]@[96x256] FFMA2 GEMM
// SMEM (floats): W2 24576 | attDup 64*97 u64 (=12416 f) | ts 2304 | us 96
// ===========================================================================
#define SM_W2      0
#define SM_ATT     24576                    // float offset; u64-aligned
#define ATT_PITCH64 97                      // u64 pitch per row (pad vs banks)
#define SM_TS      (SM_ATT + 64 * ATT_PITCH64 * 2)   // 36992
#define SM_US      (SM_TS + T_SLOTS * J_DIM)         // 39296
#define SM_FLOATS  (SM_US + J_DIM)                   // 39392
#define SM_BYTES   (SM_FLOATS * 4)                   // 157568

__global__ __launch_bounds__(256, 1) void main_kernel(
    const int* __restrict__ hour, const int* __restrict__ hmask,
    const float* __restrict__ bu, float* __restrict__ out)
{
    extern __shared__ float sm[];
    float* sW2  = sm + SM_W2;
    u64*   sAtt = (u64*)(sm + SM_ATT);
    float* sTs  = sm + SM_TS;
    float* sUs  = sm + SM_US;

    int tid = threadIdx.x;
    int n0  = blockIdx.x * 64;
    int b   = n0 >> 7;            // 64 | 128 -> whole block in one batch row

    // cooperative loads
    {
        const float4* s1 = (const float4*)g_W2;
        float4* d1 = (float4*)sW2;
        #pragma unroll
        for (int i = 0; i < 24; i++) d1[tid + i * 256] = s1[tid + i * 256];
        const float4* s2 = (const float4*)g_ts;
        float4* d2 = (float4*)sTs;
        for (int i = tid; i < (T_SLOTS * J_DIM) / 4; i += 256) d2[i] = s2[i];
        if (tid < J_DIM / 4)
            ((float4*)sUs)[tid] = ((const float4*)(g_us + b * J_DIM))[tid];
    }
    __syncthreads();

    // ---- phase 1: one thread per (row, head) masked softmax, dup-stored ----
    {
        int r = tid >> 2, h = tid & 3;
        int n = n0 + r;
        int hh = __ldg(hour + n);
        int msk[T_SLOTS];
        const int4* mp = (const int4*)(hmask + (size_t)n * T_SLOTS);
        #pragma unroll
        for (int i = 0; i < 6; i++) {
            int4 q = mp[i];
            msk[4*i] = q.x; msk[4*i+1] = q.y; msk[4*i+2] = q.z; msk[4*i+3] = q.w;
        }
        const float* usb = sUs + h * T_SLOTS;
        const float* tsb = sTs + hh * J_DIM + h * T_SLOTS;
        float sc[T_SLOTS];
        float mx = -3.0e38f;
        #pragma unroll
        for (int t = 0; t < T_SLOTS; t++) {
            sc[t] = msk[t] ? -1e9f : (usb[t] + tsb[t]);
            mx = fmaxf(mx, sc[t]);
        }
        float s = 0.0f;
        #pragma unroll
        for (int t = 0; t < T_SLOTS; t++) {
            float e = __expf(sc[t] - mx);
            sc[t] = e; s += e;
        }
        float inv = 1.0f / s;
        u64* ar = sAtt + r * ATT_PITCH64 + h * T_SLOTS;
        #pragma unroll
        for (int t = 0; t < T_SLOTS; t++) ar[t] = pack_dup(sc[t] * inv);
    }
    __syncthreads();

    // ---- phase 2: [64 x 96] @ [96 x 256] ----
    // Thread (rg,cg): rows rg*4..+3; u128 weight cols {cg + 16i : i<4}
    // (f32 cols 4*(cg+16i)..+3). Lanes 0-15 stream consecutive u128
    // (conflict-free), lanes 16-31 broadcast. att read as LDS.64 dup pairs.
    int rg = tid >> 4, cg = tid & 15;
    int r0 = rg * 4;
    u64 acc[4][4][2];
    #pragma unroll
    for (int i = 0; i < 4; i++) {
        float4 bv = __ldg((const float4*)bu + cg + 16 * i);
        u64 blo = pack2(bv.x, bv.y), bhi = pack2(bv.z, bv.w);
        #pragma unroll
        for (int rr = 0; rr < 4; rr++) { acc[rr][i][0] = blo; acc[rr][i][1] = bhi; }
    }
    const ulonglong2* w2p = (const ulonglong2*)sW2;
    const u64* ap = sAtt + r0 * ATT_PITCH64;
    #pragma unroll 4
    for (int j = 0; j < J_DIM; j++) {
        ulonglong2 w[4];
        #pragma unroll
        for (int i = 0; i < 4; i++) w[i] = w2p[j * (D_MODEL / 4) + cg + 16 * i];
        #pragma unroll
        for (int rr = 0; rr < 4; rr++) {
            u64 a = ap[rr * ATT_PITCH64 + j];
            #pragma unroll
            for (int i = 0; i < 4; i++) {
                fma2(acc[rr][i][0], a, w[i].x);
                fma2(acc[rr][i][1], a, w[i].y);
            }
        }
    }
    #pragma unroll
    for (int rr = 0; rr < 4; rr++) {
        float4* orow = (float4*)(out + (size_t)(n0 + r0 + rr) * D_MODEL);
        #pragma unroll
        for (int i = 0; i < 4; i++) {
            float2 lo = unpack2(acc[rr][i][0]);
            float2 hi = unpack2(acc[rr][i][1]);
            orow[cg + 16 * i] = make_float4(lo.x, lo.y, hi.x, hi.y);
        }
    }
}

extern "C" void kernel_launch(void* const* d_in, const int* in_sizes, int n_in,
                              void* d_out, int out_size) {
    const float* ts_emb = (const float*)d_in[0];
    const int*   user   = (const int*)  d_in[1];
    const int*   hour   = (const int*)  d_in[2];
    const int*   hmask  = (const int*)  d_in[3];
    const float* upt    = (const float*)d_in[4];
    const float* Wq     = (const float*)d_in[5];
    const float* bq     = (const float*)d_in[6];
    const float* Wk     = (const float*)d_in[7];
    const float* bk     = (const float*)d_in[8];
    const float* Wv     = (const float*)d_in[9];
    const float* bv     = (const float*)d_in[10];
    const float* Wu     = (const float*)d_in[11];
    const float* bu     = (const float*)d_in[12];
    float* out = (float*)d_out;

    preA<<<72 + 128, 256>>>(ts_emb, Wk, bk, Wv, bv, Wq, bq, user, upt);
    preB<<<96 + 9 + 192, 256>>>(Wu);

    cudaFuncSetAttribute(main_kernel, cudaFuncAttributeMaxDynamicSharedMemorySize, SM_BYTES);
    main_kernel<<<N_ROWS / 64, 256, SM_BYTES>>>(hour, hmask, bu, out);
}